// round 14
// baseline (speedup 1.0000x reference)
#include <cuda_runtime.h>
#include <cuda_fp16.h>
#include <cstdint>

#define NS     8192
#define TSTEPS 72

typedef unsigned long long u64;
typedef unsigned int       u32;
typedef unsigned short     u16;

// ---------------- scratch (device globals; no allocation allowed) ----------
__device__ u16   g_xt_obs[TSTEPS * 32 * NS];   // [T][C1][N] fp16
__device__ u16   g_xt_wrf[TSTEPS * 56 * NS];   // [T][C2][N] fp16
__device__ float g_featT[128 * NS];            // [128][N]

// ---------------- smem layout (bytes) for LSTM kernel ----------------------
#define SM_AH    0          // h [4 groups][32x64] fp16 sample-major, 4x4 KB
#define SM_BH    16384      // Whh [256x64] fp16, 32 KB
#define SM_BX    49152      // Wih [256x64] fp16, 32 KB
#define SM_ST0   81920      // stage buf0: [4 groups][64 ch rows x 80B]
#define STG_GRP  5120       // 64 rows x 80 B
#define STG_BUF  20480      // 4 groups
#define SM_ST1   102400     // stage buf1
#define SM_TOTAL 122880

// ---------------- math helpers ---------------------------------------------
__device__ __forceinline__ float tanh_a(float x) {
    float y; asm("tanh.approx.f32 %0, %1;" : "=f"(y) : "f"(x)); return y;
}
__device__ __forceinline__ float sigm_a(float x) {
    return fmaf(0.5f, tanh_a(0.5f * x), 0.5f);
}

// ---------------- PTX helpers -----------------------------------------------
__device__ __forceinline__ u32 smem_u32(const void* p) {
    u32 a;
    asm("{ .reg .u64 t; cvta.to.shared.u64 t, %1; cvt.u32.u64 %0, t; }" : "=r"(a) : "l"(p));
    return a;
}
__device__ __forceinline__ void cp_async16(char* smem_dst, const void* gsrc) {
    u32 sa = smem_u32(smem_dst);
    asm volatile("cp.async.ca.shared.global [%0], [%1], 16;\n" :: "r"(sa), "l"(gsrc));
}
__device__ __forceinline__ void cp_commit()   { asm volatile("cp.async.commit_group;\n"); }
__device__ __forceinline__ void cp_wait_all() { asm volatile("cp.async.wait_all;\n"); }

__device__ __forceinline__ void ldsm4(u32& r0, u32& r1, u32& r2, u32& r3, u32 addr) {
    asm volatile("ldmatrix.sync.aligned.m8n8.x4.shared.b16 {%0,%1,%2,%3}, [%4];"
                 : "=r"(r0), "=r"(r1), "=r"(r2), "=r"(r3) : "r"(addr));
}
__device__ __forceinline__ void ldsm4t(u32& r0, u32& r1, u32& r2, u32& r3, u32 addr) {
    asm volatile("ldmatrix.sync.aligned.m8n8.x4.trans.shared.b16 {%0,%1,%2,%3}, [%4];"
                 : "=r"(r0), "=r"(r1), "=r"(r2), "=r"(r3) : "r"(addr));
}
__device__ __forceinline__ void mma_fp16(float& d0, float& d1, float& d2, float& d3,
                                         u32 a0, u32 a1, u32 a2, u32 a3,
                                         u32 b0, u32 b1) {
    asm volatile("mma.sync.aligned.m16n8k16.row.col.f32.f16.f16.f32 "
                 "{%0,%1,%2,%3}, {%4,%5,%6,%7}, {%8,%9}, {%0,%1,%2,%3};"
                 : "+f"(d0), "+f"(d1), "+f"(d2), "+f"(d3)
                 : "r"(a0), "r"(a1), "r"(a2), "r"(a3), "r"(b0), "r"(b1));
}

// sample-major: row stride 128B, 16B chunk index ^= (row&7)
__device__ __forceinline__ u32 swz(u32 row, u32 chunk) {
    return row * 128u + ((chunk ^ (row & 7u)) << 4);
}

// B row permutation: gate-quad-aligned fragment ownership
__device__ __forceinline__ int brow(int g) {
    int q = g >> 6, j = g & 63;
    int warpN = j >> 4, jl = j & 15;
    int hi = jl >> 3, a = (jl & 7) >> 1, e = jl & 1;
    return warpN * 64 + 8 * (q + 4 * hi) + 2 * a + e;
}

// group-scoped barrier: 128 threads, ids 1..4
#define GBAR(id) asm volatile("bar.sync %0, 128;" :: "r"(id) : "memory")

// ---------------- kernel 1: transpose [N][C][T] -> [T][C][N] fp16 -----------
__global__ void athx_transpose_kernel(const float* __restrict__ in, int C, int which) {
    __shared__ float tile[32][65];
    u16* out = which ? g_xt_wrf : g_xt_obs;
    const int c  = blockIdx.z;
    const int n0 = blockIdx.x * 64;
    const int t0 = blockIdx.y * 32;
    const int tx = threadIdx.x, ty = threadIdx.y;  // 32 x 8
    if (t0 + tx < TSTEPS) {
        #pragma unroll
        for (int r = 0; r < 8; ++r) {
            int n = ty + r * 8;
            tile[tx][n] = in[((size_t)(n0 + n) * C + c) * TSTEPS + t0 + tx];
        }
    }
    __syncthreads();
    #pragma unroll
    for (int rr = 0; rr < 4; ++rr) {
        int tl = ty + 8 * rr;
        int t = t0 + tl;
        if (t < TSTEPS) {
            __half2 h2 = __floats2half2_rn(tile[tl][2 * tx], tile[tl][2 * tx + 1]);
            *(u32*)(&out[((size_t)t * C + c) * NS + n0 + 2 * tx]) = *(u32*)&h2;
        }
    }
}

// ---------------- kernel 2: HMMA dual-LSTM, 4-group anti-phase (R12) --------
__global__ __launch_bounds__(512, 1)
void athx_lstm_mma(const float* __restrict__ oWih, const float* __restrict__ oWhh,
                   const float* __restrict__ obih, const float* __restrict__ obhh,
                   const float* __restrict__ wWih, const float* __restrict__ wWhh,
                   const float* __restrict__ wbih, const float* __restrict__ wbhh)
{
    extern __shared__ char smem[];
    const bool wrf = (blockIdx.x >= 64);
    const int  C   = wrf ? 56 : 32;
    const int  KCX = wrf ? 4 : 2;         // x k-chunks (16 cols each)
    const u16* xt = wrf ? g_xt_wrf : g_xt_obs;
    const float* Wih = wrf ? wWih : oWih;
    const float* Whh = wrf ? wWhh : oWhh;
    const float* bih = wrf ? wbih : obih;
    const float* bhh = wrf ? wbhh : obhh;
    const int n0  = (blockIdx.x & 63) * 128;
    const int tid = threadIdx.x;
    const int lane = tid & 31;
    const int grp  = tid >> 7;            // 0..3 (4 warps each)
    const int tg   = tid & 127;           // thread-in-group
    const int warpN = (tid >> 5) & 3;     // warp-in-group = gate column group

    const u32 smb = smem_u32(smem);
    const int barid = 1 + grp;

#define XFETCH(TIDX, STG_OFF)                                                    \
    {                                                                            \
        const u16* src = xt + (size_t)(TIDX) * C * NS + n0 + grp * 32;           \
        char* dst = smem + (STG_OFF) + grp * STG_GRP;                            \
        for (int i = tg; i < C * 4; i += 128) {                                  \
            int ch = i >> 2, j = i & 3;                                          \
            cp_async16(dst + ch * 80 + j * 16,                                   \
                       src + (size_t)ch * NS + j * 8);                           \
        }                                                                        \
        cp_commit();                                                             \
    }

    for (int i = tid; i < SM_TOTAL / 16; i += 512)
        ((uint4*)smem)[i] = make_uint4(0, 0, 0, 0);
    __syncthreads();

    XFETCH(0, SM_ST0)

    for (int i = tid; i < 256 * 64; i += 512) {
        int g = i >> 6, k = i & 63;
        u32 off = swz((u32)brow(g), (u32)(k >> 3)) + (k & 7) * 2;
        *(__half*)(smem + SM_BH + off) = __float2half_rn(Whh[i]);
    }
    for (int i = tid; i < 256 * C; i += 512) {
        int g = i / C, ch = i - g * C;
        u32 off = swz((u32)brow(g), (u32)(ch >> 3)) + (ch & 7) * 2;
        *(__half*)(smem + SM_BX + off) = __float2half_rn(Wih[i]);
    }

    const int jbase = warpN * 16 + (lane & 3) * 2;
    float breg[16];
    #pragma unroll
    for (int q = 0; q < 4; ++q)
        #pragma unroll
        for (int h2i = 0; h2i < 2; ++h2i)
            #pragma unroll
            for (int e = 0; e < 2; ++e) {
                int g = q * 64 + jbase + h2i * 8 + e;
                breg[q * 4 + h2i * 2 + e] = bih[g] + bhh[g];
            }

    cp_wait_all();
    __syncthreads();

    const int g8 = lane >> 3, l = lane & 7;
    const u32 aRow = (u32)((g8 & 1) * 8 + l);
    const u32 bRow = (u32)(warpN * 64 + ((g8 >> 1) & 1) * 8 + l);
    const u32 gAc = (u32)(g8 >> 1);
    const u32 gBc = (u32)(g8 & 1);
    const u32 lx = (u32)l;
    const u32 aB  = smb + SM_AH + (u32)grp * 4096u + aRow * 128;
    const u32 bhB = smb + SM_BH + bRow * 128;
    const u32 bxB = smb + SM_BX + bRow * 128;
    const u32 stRowB = (u32)(gAc * 8 + (u32)l) * 80u;
    const u32 sxT0 = ((u32)(g8 & 1)) << 4;
    const u32 sxT1 = sxT0 + 32u;

    float acc[2][8][4];
    float cst[16];
    #pragma unroll
    for (int i = 0; i < 16; ++i) cst[i] = 0.0f;

#define MMA1(A_B, B_B, KC)                                                              \
    for (int ks = 0; ks < (KC); ++ks) {                                                 \
        u32 a[8];                                                                       \
        u32 ca = ((2u * ks + gAc) ^ lx) << 4;                                           \
        ldsm4(a[0], a[1], a[2], a[3], (A_B) + ca);                                      \
        ldsm4(a[4], a[5], a[6], a[7], (A_B) + 2048 + ca);                               \
        u32 cb = ((2u * ks + gBc) ^ lx) << 4;                                           \
        _Pragma("unroll")                                                               \
        for (int ntp = 0; ntp < 4; ++ntp) {                                             \
            u32 b0, b1, b2, b3;                                                         \
            ldsm4(b0, b1, b2, b3, (B_B) + ntp * 2048 + cb);                             \
            _Pragma("unroll")                                                           \
            for (int mt = 0; mt < 2; ++mt) {                                            \
                mma_fp16(acc[mt][2*ntp][0], acc[mt][2*ntp][1], acc[mt][2*ntp][2], acc[mt][2*ntp][3], \
                         a[4*mt], a[4*mt+1], a[4*mt+2], a[4*mt+3], b0, b1);             \
                mma_fp16(acc[mt][2*ntp+1][0], acc[mt][2*ntp+1][1], acc[mt][2*ntp+1][2], acc[mt][2*ntp+1][3], \
                         a[4*mt], a[4*mt+1], a[4*mt+2], a[4*mt+3], b2, b3);             \
            }                                                                           \
        }                                                                               \
    }

#define MMA1T(STG_ABS, B_B, KC)                                                         \
    for (int ks = 0; ks < (KC); ++ks) {                                                 \
        u32 a[8];                                                                       \
        u32 ab = (STG_ABS) + stRowB + (u32)ks * 1280u;                                  \
        ldsm4t(a[0], a[1], a[2], a[3], ab + sxT0);                                      \
        ldsm4t(a[4], a[5], a[6], a[7], ab + sxT1);                                      \
        u32 cb = ((2u * ks + gBc) ^ lx) << 4;                                           \
        _Pragma("unroll")                                                               \
        for (int ntp = 0; ntp < 4; ++ntp) {                                             \
            u32 b0, b1, b2, b3;                                                         \
            ldsm4(b0, b1, b2, b3, (B_B) + ntp * 2048 + cb);                             \
            _Pragma("unroll")                                                           \
            for (int mt = 0; mt < 2; ++mt) {                                            \
                mma_fp16(acc[mt][2*ntp][0], acc[mt][2*ntp][1], acc[mt][2*ntp][2], acc[mt][2*ntp][3], \
                         a[4*mt], a[4*mt+1], a[4*mt+2], a[4*mt+3], b0, b1);             \
                mma_fp16(acc[mt][2*ntp+1][0], acc[mt][2*ntp+1][1], acc[mt][2*ntp+1][2], acc[mt][2*ntp+1][3], \
                         a[4*mt], a[4*mt+1], a[4*mt+2], a[4*mt+3], b2, b3);             \
            }                                                                           \
        }                                                                               \
    }

#define ZERO_ACC()                                                                      \
    _Pragma("unroll")                                                                   \
    for (int mt = 0; mt < 2; ++mt)                                                      \
        _Pragma("unroll")                                                               \
        for (int nt = 0; nt < 8; ++nt)                                                  \
            _Pragma("unroll")                                                           \
            for (int r = 0; r < 4; ++r) acc[mt][nt][r] = 0.0f;

    ZERO_ACC()
    MMA1T(smb + SM_ST0 + (u32)grp * STG_GRP, bxB, KCX)

    for (int t = 0; t < TSTEPS; ++t) {
        GBAR(barid);

        if (t + 1 < TSTEPS) {
            XFETCH(t + 1, ((t + 1) & 1) ? SM_ST1 : SM_ST0)
        }

        MMA1(aB, bhB, 4)

        float hval[16];
        #pragma unroll
        for (int mt = 0; mt < 2; ++mt)
            #pragma unroll
            for (int d = 0; d < 2; ++d)
                #pragma unroll
                for (int h2i = 0; h2i < 2; ++h2i)
                    #pragma unroll
                    for (int e = 0; e < 2; ++e) {
                        int r = 2 * d + e;
                        int ci = ((mt * 2 + d) * 2 + h2i) * 2 + e;
                        int bi = h2i * 2 + e;
                        float gi = sigm_a(acc[mt][4*h2i + 0][r] + breg[bi]);
                        float gf = sigm_a(acc[mt][4*h2i + 1][r] + breg[4 + bi]);
                        float gg = tanh_a(acc[mt][4*h2i + 2][r] + breg[8 + bi]);
                        float go = sigm_a(acc[mt][4*h2i + 3][r] + breg[12 + bi]);
                        float cc = fmaf(gf, cst[ci], gi * gg);
                        cst[ci] = cc;
                        hval[ci] = go * tanh_a(cc);
                    }

        cp_wait_all();
        GBAR(barid);

        if (t == TSTEPS - 1) {
            const int off = wrf ? 64 : 0;
            #pragma unroll
            for (int mt = 0; mt < 2; ++mt)
                #pragma unroll
                for (int d = 0; d < 2; ++d)
                    #pragma unroll
                    for (int h2i = 0; h2i < 2; ++h2i)
                        #pragma unroll
                        for (int e = 0; e < 2; ++e) {
                            int s = grp * 32 + mt * 16 + (lane >> 2) + 8 * d;
                            int j = warpN * 16 + h2i * 8 + (lane & 3) * 2 + e;
                            int ci = ((mt * 2 + d) * 2 + h2i) * 2 + e;
                            g_featT[(size_t)(off + j) * NS + n0 + s] = hval[ci];
                        }
        } else {
            #pragma unroll
            for (int mt = 0; mt < 2; ++mt)
                #pragma unroll
                for (int d = 0; d < 2; ++d)
                    #pragma unroll
                    for (int h2i = 0; h2i < 2; ++h2i) {
                        int ci = ((mt * 2 + d) * 2 + h2i) * 2;
                        __half hh0 = __float2half_rn(hval[ci]);
                        __half hh1 = __float2half_rn(hval[ci + 1]);
                        u32 hi32 = (u32)__half_as_ushort(hh0) | ((u32)__half_as_ushort(hh1) << 16);
                        u32 s  = (u32)(mt * 16 + (lane >> 2) + 8 * d);
                        u32 jp = (u32)(warpN * 16 + h2i * 8 + (lane & 3) * 2);
                        u32 off = (u32)grp * 4096u + swz(s, jp >> 3) + (jp & 7) * 2;
                        *(u32*)(smem + SM_AH + off) = hi32;
                    }
            ZERO_ACC()
            MMA1T((((t + 1) & 1) ? (smb + SM_ST1) : (smb + SM_ST0)) + (u32)grp * STG_GRP,
                  bxB, KCX)
        }
    }
#undef MMA1
#undef MMA1T
#undef ZERO_ACC
#undef XFETCH
}

// ---------------- kernel 3: MLP heads — 64 samples/CTA, 2 CTAs/SM -----------
#define SPAD2 66
__device__ __forceinline__ u64 dup2(float x) {
    u64 r; asm("mov.b64 %0, {%1,%1};" : "=l"(r) : "f"(x)); return r;
}
__device__ __forceinline__ void unpack2(u64 v, float& x, float& y) {
    asm("mov.b64 {%0,%1}, %2;" : "=f"(x), "=f"(y) : "l"(v));
}
__device__ __forceinline__ u64 ffma2(u64 a, u64 b, u64 c) {
    u64 d; asm("fma.rn.f32x2 %0, %1, %2, %3;" : "=l"(d) : "l"(a), "l"(b), "l"(c)); return d;
}

// GX output-groups; 64 samples; weights fp16 in smem, fp32 accumulate
template <int IN, int OUT, int GX, bool RELU>
__device__ __forceinline__ void athx_layerh(const float* __restrict__ A,
                                            const __half* __restrict__ wt,
                                            const float* __restrict__ bs,
                                            float* __restrict__ Bout,
                                            int tid) {
    const int gx = tid & (GX - 1);
    const int sx = tid / GX;
    constexpr int NSX = 512 / GX;
    constexpr int SPT = 64 / NSX;
    constexpr int PAIRS = SPT / 2;
    constexpr int R = OUT / GX;
    u64 acc2[PAIRS][R];
    #pragma unroll
    for (int p = 0; p < PAIRS; ++p)
        #pragma unroll
        for (int r = 0; r < R; ++r) acc2[p][r] = 0ull;
    for (int k = 0; k < IN; ++k) {
        u64 a2[PAIRS];
        #pragma unroll
        for (int p = 0; p < PAIRS; ++p)
            a2[p] = *(const u64*)(A + k * SPAD2 + sx * SPT + 2 * p);
        #pragma unroll
        for (int r = 0; r < R; ++r) {
            u64 b2 = dup2(__half2float(wt[k * OUT + gx + GX * r]));
            #pragma unroll
            for (int p = 0; p < PAIRS; ++p) acc2[p][r] = ffma2(a2[p], b2, acc2[p][r]);
        }
    }
    #pragma unroll
    for (int r = 0; r < R; ++r) {
        int u = gx + GX * r;
        float bb = bs[u];
        #pragma unroll
        for (int p = 0; p < PAIRS; ++p) {
            float v0, v1;
            unpack2(acc2[p][r], v0, v1);
            v0 += bb; v1 += bb;
            if (RELU) { v0 = fmaxf(v0, 0.0f); v1 = fmaxf(v1, 0.0f); }
            *(float2*)(Bout + u * SPAD2 + sx * SPT + 2 * p) = make_float2(v0, v1);
        }
    }
}

__global__ __launch_bounds__(512, 2) void athx_head_kernel(
    const float* __restrict__ fW1, const float* __restrict__ fb1,
    const float* __restrict__ fW2, const float* __restrict__ fb2,
    const float* __restrict__ fW3, const float* __restrict__ fb3,
    const float* __restrict__ oW1, const float* __restrict__ ob1,
    const float* __restrict__ oW2, const float* __restrict__ ob2,
    const float* __restrict__ oW3, const float* __restrict__ ob3,
    float* __restrict__ out)
{
    extern __shared__ float sm[];
    float*  A   = sm;                              // [128][SPAD2] fp32
    float*  B   = A + 128 * SPAD2;                 // [96][SPAD2] fp32
    __half* w1t = (__half*)(B + 96 * SPAD2);       // [128][96] fp16
    __half* w2t = w1t + 128 * 96;                  // [96][64]
    __half* w3t = w2t + 96 * 64;                   // [64][48]
    float*  bs1 = (float*)(w3t + 64 * 48);         // 96
    float*  bs2 = bs1 + 96;                        // 64
    float*  bs3 = bs2 + 64;                        // 48

    const int head = blockIdx.y;
    const float* W1 = head ? oW1 : fW1; const float* b1 = head ? ob1 : fb1;
    const float* W2 = head ? oW2 : fW2; const float* b2 = head ? ob2 : fb2;
    const float* W3 = head ? oW3 : fW3; const float* b3 = head ? ob3 : fb3;
    const int n0  = blockIdx.x * 64;
    const int tid = threadIdx.x;

    for (int idx = tid; idx < 128 * 64; idx += 512) {
        int k = idx >> 6, s = idx & 63;
        A[k * SPAD2 + s] = g_featT[(size_t)k * NS + n0 + s];
    }
    for (int idx = tid; idx < 96 * 128; idx += 512) {
        int u = idx >> 7, k = idx & 127;
        w1t[k * 96 + u] = __float2half_rn(W1[idx]);
    }
    for (int idx = tid; idx < 64 * 96; idx += 512) {
        int u = idx / 96, k = idx - u * 96;
        w2t[k * 64 + u] = __float2half_rn(W2[idx]);
    }
    for (int idx = tid; idx < 48 * 64; idx += 512) {
        int u = idx >> 6, k = idx & 63;
        w3t[k * 48 + u] = __float2half_rn(W3[idx]);
    }
    if (tid < 96) bs1[tid] = b1[tid];
    if (tid < 64) bs2[tid] = b2[tid];
    if (tid < 48) bs3[tid] = b3[tid];
    __syncthreads();

    athx_layerh<128, 96, 32, true>(A, w1t, bs1, B, tid);
    __syncthreads();
    athx_layerh<96, 64, 32, true>(B, w2t, bs2, A, tid);
    __syncthreads();

    // layer 3 (64 -> 48): GX=16, 2 samples/thread, write to gmem
    {
        const int gx = tid & 15;
        const int sx = tid >> 4;        // 0..31, 2 samples each
        u64 acc2[3];
        #pragma unroll
        for (int r = 0; r < 3; ++r) acc2[r] = 0ull;
        for (int k = 0; k < 64; ++k) {
            u64 a2 = *(const u64*)(A + k * SPAD2 + sx * 2);
            #pragma unroll
            for (int r = 0; r < 3; ++r)
                acc2[r] = ffma2(a2, dup2(__half2float(w3t[k * 48 + gx + 16 * r])), acc2[r]);
        }
        #pragma unroll
        for (int r = 0; r < 3; ++r) {
            int u = gx + 16 * r;
            float bb = bs3[u];
            float v0, v1;
            unpack2(acc2[r], v0, v1);
            int n = n0 + sx * 2;
            out[(size_t)n * 96 + head * 48 + u]       = v0 + bb;
            out[(size_t)(n + 1) * 96 + head * 48 + u] = v1 + bb;
        }
    }
}

// ---------------- launch ----------------------------------------------------
extern "C" void kernel_launch(void* const* d_in, const int* in_sizes, int n_in,
                              void* d_out, int out_size) {
    const float* X_obs  = (const float*)d_in[0];
    const float* X_wrf  = (const float*)d_in[1];
    const float* oWih   = (const float*)d_in[2];
    const float* oWhh   = (const float*)d_in[3];
    const float* obih   = (const float*)d_in[4];
    const float* obhh   = (const float*)d_in[5];
    const float* wWih   = (const float*)d_in[6];
    const float* wWhh   = (const float*)d_in[7];
    const float* wbih   = (const float*)d_in[8];
    const float* wbhh   = (const float*)d_in[9];
    const float* fW1 = (const float*)d_in[10]; const float* fb1 = (const float*)d_in[11];
    const float* fW2 = (const float*)d_in[12]; const float* fb2 = (const float*)d_in[13];
    const float* fW3 = (const float*)d_in[14]; const float* fb3 = (const float*)d_in[15];
    const float* oW1 = (const float*)d_in[16]; const float* ob1 = (const float*)d_in[17];
    const float* oW2 = (const float*)d_in[18]; const float* ob2 = (const float*)d_in[19];
    const float* oW3 = (const float*)d_in[20]; const float* ob3 = (const float*)d_in[21];
    float* out = (float*)d_out;

    const int HEAD_SMEM = (128 * SPAD2 + 96 * SPAD2) * 4
                        + (128 * 96 + 96 * 64 + 64 * 48) * 2
                        + (96 + 64 + 48) * 4;
    cudaFuncSetAttribute(athx_lstm_mma, cudaFuncAttributeMaxDynamicSharedMemorySize, SM_TOTAL);
    cudaFuncSetAttribute(athx_head_kernel, cudaFuncAttributeMaxDynamicSharedMemorySize, HEAD_SMEM);

    athx_transpose_kernel<<<dim3(NS / 64, 3, 32), dim3(32, 8)>>>(X_obs, 32, 0);
    athx_transpose_kernel<<<dim3(NS / 64, 3, 56), dim3(32, 8)>>>(X_wrf, 56, 1);

    athx_lstm_mma<<<128, 512, SM_TOTAL>>>(oWih, oWhh, obih, obhh,
                                          wWih, wWhh, wbih, wbhh);

    athx_head_kernel<<<dim3(NS / 64, 2), 512, HEAD_SMEM>>>(
        fW1, fb1, fW2, fb2, fW3, fb3,
        oW1, ob1, oW2, ob2, oW3, ob3, out);
}

// round 15
// speedup vs baseline: 1.0423x; 1.0423x over previous
#include <cuda_runtime.h>
#include <cuda_fp16.h>
#include <cstdint>

#define NS     8192
#define TSTEPS 72

typedef unsigned long long u64;
typedef unsigned int       u32;
typedef unsigned short     u16;

// ---------------- scratch (device globals; no allocation allowed) ----------
__device__ u16   g_xt_obs[TSTEPS * 32 * NS];   // [T][C1][N] fp16
__device__ u16   g_xt_wrf[TSTEPS * 56 * NS];   // [T][C2][N] fp16
__device__ float g_featT[128 * NS];            // [128][N]

// ---------------- smem layout (bytes) for LSTM kernel ----------------------
#define SM_AH    0          // h [2 bufs][4 groups][32x64] fp16, 2x16 KB
#define SM_BH    32768      // Whh [256x64] fp16, 32 KB
#define SM_BX    65536      // Wih [256x64] fp16, 32 KB
#define SM_ST0   98304      // stage buf0: [4 groups][64 ch rows x 80B]
#define STG_GRP  5120       // 64 rows x 80 B
#define STG_BUF  20480      // 4 groups
#define SM_ST1   118784     // stage buf1
#define SM_TOTAL 139264

// ---------------- math helpers ---------------------------------------------
__device__ __forceinline__ float tanh_a(float x) {
    float y; asm("tanh.approx.f32 %0, %1;" : "=f"(y) : "f"(x)); return y;
}
__device__ __forceinline__ float sigm_a(float x) {
    return fmaf(0.5f, tanh_a(0.5f * x), 0.5f);
}

// ---------------- PTX helpers -----------------------------------------------
__device__ __forceinline__ u32 smem_u32(const void* p) {
    u32 a;
    asm("{ .reg .u64 t; cvta.to.shared.u64 t, %1; cvt.u32.u64 %0, t; }" : "=r"(a) : "l"(p));
    return a;
}
__device__ __forceinline__ void cp_async16(char* smem_dst, const void* gsrc) {
    u32 sa = smem_u32(smem_dst);
    asm volatile("cp.async.ca.shared.global [%0], [%1], 16;\n" :: "r"(sa), "l"(gsrc));
}
__device__ __forceinline__ void cp_commit()   { asm volatile("cp.async.commit_group;\n"); }
__device__ __forceinline__ void cp_wait_all() { asm volatile("cp.async.wait_all;\n"); }

__device__ __forceinline__ void ldsm4(u32& r0, u32& r1, u32& r2, u32& r3, u32 addr) {
    asm volatile("ldmatrix.sync.aligned.m8n8.x4.shared.b16 {%0,%1,%2,%3}, [%4];"
                 : "=r"(r0), "=r"(r1), "=r"(r2), "=r"(r3) : "r"(addr));
}
__device__ __forceinline__ void ldsm4t(u32& r0, u32& r1, u32& r2, u32& r3, u32 addr) {
    asm volatile("ldmatrix.sync.aligned.m8n8.x4.trans.shared.b16 {%0,%1,%2,%3}, [%4];"
                 : "=r"(r0), "=r"(r1), "=r"(r2), "=r"(r3) : "r"(addr));
}
__device__ __forceinline__ void mma_fp16(float& d0, float& d1, float& d2, float& d3,
                                         u32 a0, u32 a1, u32 a2, u32 a3,
                                         u32 b0, u32 b1) {
    asm volatile("mma.sync.aligned.m16n8k16.row.col.f32.f16.f16.f32 "
                 "{%0,%1,%2,%3}, {%4,%5,%6,%7}, {%8,%9}, {%0,%1,%2,%3};"
                 : "+f"(d0), "+f"(d1), "+f"(d2), "+f"(d3)
                 : "r"(a0), "r"(a1), "r"(a2), "r"(a3), "r"(b0), "r"(b1));
}

// sample-major: row stride 128B, 16B chunk index ^= (row&7)
__device__ __forceinline__ u32 swz(u32 row, u32 chunk) {
    return row * 128u + ((chunk ^ (row & 7u)) << 4);
}

// B row permutation: gate-quad-aligned fragment ownership
__device__ __forceinline__ int brow(int g) {
    int q = g >> 6, j = g & 63;
    int warpN = j >> 4, jl = j & 15;
    int hi = jl >> 3, a = (jl & 7) >> 1, e = jl & 1;
    return warpN * 64 + 8 * (q + 4 * hi) + 2 * a + e;
}

// group-scoped barrier: 128 threads, ids 1..4
#define GBAR(id) asm volatile("bar.sync %0, 128;" :: "r"(id) : "memory")

// ---------------- kernel 1: transpose [N][C][T] -> [T][C][N] fp16 -----------
__global__ void athx_transpose_kernel(const float* __restrict__ in, int C, int which) {
    __shared__ float tile[32][65];
    u16* out = which ? g_xt_wrf : g_xt_obs;
    const int c  = blockIdx.z;
    const int n0 = blockIdx.x * 64;
    const int t0 = blockIdx.y * 32;
    const int tx = threadIdx.x, ty = threadIdx.y;  // 32 x 8
    if (t0 + tx < TSTEPS) {
        #pragma unroll
        for (int r = 0; r < 8; ++r) {
            int n = ty + r * 8;
            tile[tx][n] = in[((size_t)(n0 + n) * C + c) * TSTEPS + t0 + tx];
        }
    }
    __syncthreads();
    #pragma unroll
    for (int rr = 0; rr < 4; ++rr) {
        int tl = ty + 8 * rr;
        int t = t0 + tl;
        if (t < TSTEPS) {
            __half2 h2 = __floats2half2_rn(tile[tl][2 * tx], tile[tl][2 * tx + 1]);
            *(u32*)(&out[((size_t)t * C + c) * NS + n0 + 2 * tx]) = *(u32*)&h2;
        }
    }
}

// ---------------- kernel 2: HMMA dual-LSTM, 4-group, 1 barrier/step ---------
__global__ __launch_bounds__(512, 1)
void athx_lstm_mma(const float* __restrict__ oWih, const float* __restrict__ oWhh,
                   const float* __restrict__ obih, const float* __restrict__ obhh,
                   const float* __restrict__ wWih, const float* __restrict__ wWhh,
                   const float* __restrict__ wbih, const float* __restrict__ wbhh)
{
    extern __shared__ char smem[];
    const bool wrf = (blockIdx.x >= 64);
    const int  C   = wrf ? 56 : 32;
    const int  KCX = wrf ? 4 : 2;         // x k-chunks (16 cols each)
    const u16* xt = wrf ? g_xt_wrf : g_xt_obs;
    const float* Wih = wrf ? wWih : oWih;
    const float* Whh = wrf ? wWhh : oWhh;
    const float* bih = wrf ? wbih : obih;
    const float* bhh = wrf ? wbhh : obhh;
    const int n0  = (blockIdx.x & 63) * 128;
    const int tid = threadIdx.x;
    const int lane = tid & 31;
    const int grp  = tid >> 7;            // 0..3 (4 warps each)
    const int tg   = tid & 127;           // thread-in-group
    const int warpN = (tid >> 5) & 3;     // warp-in-group = gate column group

    const u32 smb = smem_u32(smem);
    const int barid = 1 + grp;

#define XFETCH(TIDX, STG_OFF)                                                    \
    {                                                                            \
        const u16* src = xt + (size_t)(TIDX) * C * NS + n0 + grp * 32;           \
        char* dst = smem + (STG_OFF) + grp * STG_GRP;                            \
        for (int i = tg; i < C * 4; i += 128) {                                  \
            int ch = i >> 2, j = i & 3;                                          \
            cp_async16(dst + ch * 80 + j * 16,                                   \
                       src + (size_t)ch * NS + j * 8);                           \
        }                                                                        \
        cp_commit();                                                             \
    }

    // ---- zero ALL smem (both h bufs = 0, BX pad cols, stage pad rows) ----
    for (int i = tid; i < SM_TOTAL / 16; i += 512)
        ((uint4*)smem)[i] = make_uint4(0, 0, 0, 0);
    __syncthreads();

    // ---- prefetch x_0 (own group's quarter) ----
    XFETCH(0, SM_ST0)

    // ---- fill B_h (Whh fp16), B_x (Wih fp16) — full CTA ----
    for (int i = tid; i < 256 * 64; i += 512) {
        int g = i >> 6, k = i & 63;
        u32 off = swz((u32)brow(g), (u32)(k >> 3)) + (k & 7) * 2;
        *(__half*)(smem + SM_BH + off) = __float2half_rn(Whh[i]);
    }
    for (int i = tid; i < 256 * C; i += 512) {
        int g = i / C, ch = i - g * C;
        u32 off = swz((u32)brow(g), (u32)(ch >> 3)) + (ch & 7) * 2;
        *(__half*)(smem + SM_BX + off) = __float2half_rn(Wih[i]);
    }

    // ---- bias into registers (per-thread 16 gates, fp32) ----
    const int jbase = warpN * 16 + (lane & 3) * 2;
    float breg[16];
    #pragma unroll
    for (int q = 0; q < 4; ++q)
        #pragma unroll
        for (int h2i = 0; h2i < 2; ++h2i)
            #pragma unroll
            for (int e = 0; e < 2; ++e) {
                int g = q * 64 + jbase + h2i * 8 + e;
                breg[q * 4 + h2i * 2 + e] = bih[g] + bhh[g];
            }

    cp_wait_all();
    __syncthreads();    // B fills + zeros + all stage quarters visible

    // ---- per-thread ldmatrix geometry ----
    const int g8 = lane >> 3, l = lane & 7;
    const u32 aRow = (u32)((g8 & 1) * 8 + l);
    const u32 bRow = (u32)(warpN * 64 + ((g8 >> 1) & 1) * 8 + l);
    const u32 gAc = (u32)(g8 >> 1);
    const u32 gBc = (u32)(g8 & 1);
    const u32 lx = (u32)l;
    const u32 aGrpB = smb + SM_AH + (u32)grp * 4096u + aRow * 128;  // + buf*16384
    const u32 bhB = smb + SM_BH + bRow * 128;
    const u32 bxB = smb + SM_BX + bRow * 128;
    const u32 stRowB = (u32)(gAc * 8 + (u32)l) * 80u;
    const u32 sxT0 = ((u32)(g8 & 1)) << 4;
    const u32 sxT1 = sxT0 + 32u;

    float acc[2][8][4];
    float cst[16];
    #pragma unroll
    for (int i = 0; i < 16; ++i) cst[i] = 0.0f;

#define MMA1(A_B, B_B, KC)                                                              \
    for (int ks = 0; ks < (KC); ++ks) {                                                 \
        u32 a[8];                                                                       \
        u32 ca = ((2u * ks + gAc) ^ lx) << 4;                                           \
        ldsm4(a[0], a[1], a[2], a[3], (A_B) + ca);                                      \
        ldsm4(a[4], a[5], a[6], a[7], (A_B) + 2048 + ca);                               \
        u32 cb = ((2u * ks + gBc) ^ lx) << 4;                                           \
        _Pragma("unroll")                                                               \
        for (int ntp = 0; ntp < 4; ++ntp) {                                             \
            u32 b0, b1, b2, b3;                                                         \
            ldsm4(b0, b1, b2, b3, (B_B) + ntp * 2048 + cb);                             \
            _Pragma("unroll")                                                           \
            for (int mt = 0; mt < 2; ++mt) {                                            \
                mma_fp16(acc[mt][2*ntp][0], acc[mt][2*ntp][1], acc[mt][2*ntp][2], acc[mt][2*ntp][3], \
                         a[4*mt], a[4*mt+1], a[4*mt+2], a[4*mt+3], b0, b1);             \
                mma_fp16(acc[mt][2*ntp+1][0], acc[mt][2*ntp+1][1], acc[mt][2*ntp+1][2], acc[mt][2*ntp+1][3], \
                         a[4*mt], a[4*mt+1], a[4*mt+2], a[4*mt+3], b2, b3);             \
            }                                                                           \
        }                                                                               \
    }

#define MMA1T(STG_ABS, B_B, KC)                                                         \
    for (int ks = 0; ks < (KC); ++ks) {                                                 \
        u32 a[8];                                                                       \
        u32 ab = (STG_ABS) + stRowB + (u32)ks * 1280u;                                  \
        ldsm4t(a[0], a[1], a[2], a[3], ab + sxT0);                                      \
        ldsm4t(a[4], a[5], a[6], a[7], ab + sxT1);                                      \
        u32 cb = ((2u * ks + gBc) ^ lx) << 4;                                           \
        _Pragma("unroll")                                                               \
        for (int ntp = 0; ntp < 4; ++ntp) {                                             \
            u32 b0, b1, b2, b3;                                                         \
            ldsm4(b0, b1, b2, b3, (B_B) + ntp * 2048 + cb);                             \
            _Pragma("unroll")                                                           \
            for (int mt = 0; mt < 2; ++mt) {                                            \
                mma_fp16(acc[mt][2*ntp][0], acc[mt][2*ntp][1], acc[mt][2*ntp][2], acc[mt][2*ntp][3], \
                         a[4*mt], a[4*mt+1], a[4*mt+2], a[4*mt+3], b0, b1);             \
                mma_fp16(acc[mt][2*ntp+1][0], acc[mt][2*ntp+1][1], acc[mt][2*ntp+1][2], acc[mt][2*ntp+1][3], \
                         a[4*mt], a[4*mt+1], a[4*mt+2], a[4*mt+3], b2, b3);             \
            }                                                                           \
        }                                                                               \
    }

#define ZERO_ACC()                                                                      \
    _Pragma("unroll")                                                                   \
    for (int mt = 0; mt < 2; ++mt)                                                      \
        _Pragma("unroll")                                                               \
        for (int nt = 0; nt < 8; ++nt)                                                  \
            _Pragma("unroll")                                                           \
            for (int r = 0; r < 4; ++r) acc[mt][nt][r] = 0.0f;

    // ---- prologue x-mma: acc = Xpart_0 (from stage0, trans) ----
    ZERO_ACC()
    MMA1T(smb + SM_ST0 + (u32)grp * STG_GRP, bxB, KCX)

    for (int t = 0; t < TSTEPS; ++t) {
        // h-part: acc += h_{t-1} . Whh^T  from AH buf[t&1]
        // (h_{t-1} STS + barrier happened at end of step t-1)
        MMA1(aGrpB + (u32)(t & 1) * 16384u, bhB, 4)

        // issue x_{t+1} fetch (slot last read two barriers ago — safe)
        if (t + 1 < TSTEPS) {
            XFETCH(t + 1, ((t + 1) & 1) ? SM_ST1 : SM_ST0)
        }

        // ---- epilogue: fp32 gates, fp32 cell state ----
        float hval[16];
        #pragma unroll
        for (int mt = 0; mt < 2; ++mt)
            #pragma unroll
            for (int d = 0; d < 2; ++d)
                #pragma unroll
                for (int h2i = 0; h2i < 2; ++h2i)
                    #pragma unroll
                    for (int e = 0; e < 2; ++e) {
                        int r = 2 * d + e;
                        int ci = ((mt * 2 + d) * 2 + h2i) * 2 + e;
                        int bi = h2i * 2 + e;
                        float gi = sigm_a(acc[mt][4*h2i + 0][r] + breg[bi]);
                        float gf = sigm_a(acc[mt][4*h2i + 1][r] + breg[4 + bi]);
                        float gg = tanh_a(acc[mt][4*h2i + 2][r] + breg[8 + bi]);
                        float go = sigm_a(acc[mt][4*h2i + 3][r] + breg[12 + bi]);
                        float cc = fmaf(gf, cst[ci], gi * gg);
                        cst[ci] = cc;
                        hval[ci] = go * tanh_a(cc);
                    }

        if (t == TSTEPS - 1) {
            const int off = wrf ? 64 : 0;
            #pragma unroll
            for (int mt = 0; mt < 2; ++mt)
                #pragma unroll
                for (int d = 0; d < 2; ++d)
                    #pragma unroll
                    for (int h2i = 0; h2i < 2; ++h2i)
                        #pragma unroll
                        for (int e = 0; e < 2; ++e) {
                            int s = grp * 32 + mt * 16 + (lane >> 2) + 8 * d;
                            int j = warpN * 16 + h2i * 8 + (lane & 3) * 2 + e;
                            int ci = ((mt * 2 + d) * 2 + h2i) * 2 + e;
                            g_featT[(size_t)(off + j) * NS + n0 + s] = hval[ci];
                        }
        } else {
            // STS h_t -> AH buf[(t+1)&1] (other buffer: no WAR with h-mma(t))
            const u32 dstA = (u32)((t + 1) & 1) * 16384u + (u32)grp * 4096u;
            #pragma unroll
            for (int mt = 0; mt < 2; ++mt)
                #pragma unroll
                for (int d = 0; d < 2; ++d)
                    #pragma unroll
                    for (int h2i = 0; h2i < 2; ++h2i) {
                        int ci = ((mt * 2 + d) * 2 + h2i) * 2;
                        __half hh0 = __float2half_rn(hval[ci]);
                        __half hh1 = __float2half_rn(hval[ci + 1]);
                        u32 hi32 = (u32)__half_as_ushort(hh0) | ((u32)__half_as_ushort(hh1) << 16);
                        u32 s  = (u32)(mt * 16 + (lane >> 2) + 8 * d);
                        u32 jp = (u32)(warpN * 16 + h2i * 8 + (lane & 3) * 2);
                        u32 off = dstA + swz(s, jp >> 3) + (jp & 7) * 2;
                        *(u32*)(smem + SM_AH + off) = hi32;
                    }
            cp_wait_all();     // own x_{t+1} chunks landed
            GBAR(barid);       // single barrier: publishes stage(t+1) + h_t
            // tail x-mma for t+1 (anti-phase overlap with other groups)
            ZERO_ACC()
            MMA1T((((t + 1) & 1) ? (smb + SM_ST1) : (smb + SM_ST0)) + (u32)grp * STG_GRP,
                  bxB, KCX)
        }
    }
#undef MMA1
#undef MMA1T
#undef ZERO_ACC
#undef XFETCH
}

// ---------------- kernel 3: MLP heads (R13 version — proven best) -----------
#define SPAD 132
__device__ __forceinline__ u64 dup2(float x) {
    u64 r; asm("mov.b64 %0, {%1,%1};" : "=l"(r) : "f"(x)); return r;
}
__device__ __forceinline__ void unpack2(u64 v, float& x, float& y) {
    asm("mov.b64 {%0,%1}, %2;" : "=f"(x), "=f"(y) : "l"(v));
}
__device__ __forceinline__ u64 ffma2(u64 a, u64 b, u64 c) {
    u64 d; asm("fma.rn.f32x2 %0, %1, %2, %3;" : "=l"(d) : "l"(a), "l"(b), "l"(c)); return d;
}

template <int IN, int OUT, int GX, bool RELU>
__device__ __forceinline__ void athx_layerg(const float* __restrict__ A,
                                            const float* __restrict__ wt,
                                            const float* __restrict__ bs,
                                            float* __restrict__ Bout,
                                            int tid) {
    const int gx = tid & (GX - 1);
    const int sx = tid / GX;
    constexpr int NSX = 512 / GX;
    constexpr int SPT = 128 / NSX;
    constexpr int PAIRS = SPT / 2;
    constexpr int R = OUT / GX;
    u64 acc2[PAIRS][R];
    #pragma unroll
    for (int p = 0; p < PAIRS; ++p)
        #pragma unroll
        for (int r = 0; r < R; ++r) acc2[p][r] = 0ull;
    for (int k = 0; k < IN; ++k) {
        u64 a2[PAIRS];
        #pragma unroll
        for (int p = 0; p < PAIRS; ++p)
            a2[p] = *(const u64*)(A + k * SPAD + sx * SPT + 2 * p);
        #pragma unroll
        for (int r = 0; r < R; ++r) {
            u64 b2 = dup2(wt[k * OUT + gx + GX * r]);
            #pragma unroll
            for (int p = 0; p < PAIRS; ++p) acc2[p][r] = ffma2(a2[p], b2, acc2[p][r]);
        }
    }
    #pragma unroll
    for (int r = 0; r < R; ++r) {
        int u = gx + GX * r;
        float bb = bs[u];
        #pragma unroll
        for (int p = 0; p < PAIRS; ++p) {
            float v0, v1;
            unpack2(acc2[p][r], v0, v1);
            v0 += bb; v1 += bb;
            if (RELU) { v0 = fmaxf(v0, 0.0f); v1 = fmaxf(v1, 0.0f); }
            *(float2*)(Bout + u * SPAD + sx * SPT + 2 * p) = make_float2(v0, v1);
        }
    }
}

__global__ __launch_bounds__(512, 1) void athx_head_kernel(
    const float* __restrict__ fW1, const float* __restrict__ fb1,
    const float* __restrict__ fW2, const float* __restrict__ fb2,
    const float* __restrict__ fW3, const float* __restrict__ fb3,
    const float* __restrict__ oW1, const float* __restrict__ ob1,
    const float* __restrict__ oW2, const float* __restrict__ ob2,
    const float* __restrict__ oW3, const float* __restrict__ ob3,
    float* __restrict__ out)
{
    extern __shared__ float sm[];
    float* A   = sm;
    float* B   = A + 128 * SPAD;
    float* w1t = B + 96 * SPAD;
    float* w2t = w1t + 128 * 96;
    float* w3t = w2t + 96 * 64;
    float* bs1 = w3t + 64 * 48;
    float* bs2 = bs1 + 96;
    float* bs3 = bs2 + 64;

    const int head = blockIdx.y;
    const float* W1 = head ? oW1 : fW1; const float* b1 = head ? ob1 : fb1;
    const float* W2 = head ? oW2 : fW2; const float* b2 = head ? ob2 : fb2;
    const float* W3 = head ? oW3 : fW3; const float* b3 = head ? ob3 : fb3;
    const int n0  = blockIdx.x * 128;
    const int tid = threadIdx.x;

    for (int idx = tid; idx < 128 * 128; idx += 512) {
        int k = idx >> 7, s = idx & 127;
        A[k * SPAD + s] = g_featT[(size_t)k * NS + n0 + s];
    }
    for (int idx = tid; idx < 96 * 128; idx += 512) {
        int u = idx >> 7, k = idx & 127;
        w1t[k * 96 + u] = W1[idx];
    }
    for (int idx = tid; idx < 64 * 96; idx += 512) {
        int u = idx / 96, k = idx - u * 96;
        w2t[k * 64 + u] = W2[idx];
    }
    for (int idx = tid; idx < 48 * 64; idx += 512) {
        int u = idx >> 6, k = idx & 63;
        w3t[k * 48 + u] = W3[idx];
    }
    if (tid < 96) bs1[tid] = b1[tid];
    if (tid < 64) bs2[tid] = b2[tid];
    if (tid < 48) bs3[tid] = b3[tid];
    __syncthreads();

    athx_layerg<128, 96, 32, true>(A, w1t, bs1, B, tid);
    __syncthreads();
    athx_layerg<96, 64, 32, true>(B, w2t, bs2, A, tid);
    __syncthreads();

    {
        const int gx = tid & 15;
        const int sx = tid >> 4;
        u64 acc2[2][3];
        #pragma unroll
        for (int p = 0; p < 2; ++p)
            #pragma unroll
            for (int r = 0; r < 3; ++r) acc2[p][r] = 0ull;
        for (int k = 0; k < 64; ++k) {
            ulonglong2 pq = *(const ulonglong2*)(A + k * SPAD + sx * 4);
            u64 a2[2] = {pq.x, pq.y};
            #pragma unroll
            for (int r = 0; r < 3; ++r) {
                u64 b2 = dup2(w3t[k * 48 + gx + 16 * r]);
                #pragma unroll
                for (int p = 0; p < 2; ++p) acc2[p][r] = ffma2(a2[p], b2, acc2[p][r]);
            }
        }
        #pragma unroll
        for (int r = 0; r < 3; ++r) {
            int u = gx + 16 * r;
            float bb = bs3[u];
            #pragma unroll
            for (int p = 0; p < 2; ++p) {
                float v0, v1;
                unpack2(acc2[p][r], v0, v1);
                int n = n0 + sx * 4 + 2 * p;
                out[(size_t)n * 96 + head * 48 + u]       = v0 + bb;
                out[(size_t)(n + 1) * 96 + head * 48 + u] = v1 + bb;
            }
        }
    }
}

// ---------------- launch ----------------------------------------------------
extern "C" void kernel_launch(void* const* d_in, const int* in_sizes, int n_in,
                              void* d_out, int out_size) {
    const float* X_obs  = (const float*)d_in[0];
    const float* X_wrf  = (const float*)d_in[1];
    const float* oWih   = (const float*)d_in[2];
    const float* oWhh   = (const float*)d_in[3];
    const float* obih   = (const float*)d_in[4];
    const float* obhh   = (const float*)d_in[5];
    const float* wWih   = (const float*)d_in[6];
    const float* wWhh   = (const float*)d_in[7];
    const float* wbih   = (const float*)d_in[8];
    const float* wbhh   = (const float*)d_in[9];
    const float* fW1 = (const float*)d_in[10]; const float* fb1 = (const float*)d_in[11];
    const float* fW2 = (const float*)d_in[12]; const float* fb2 = (const float*)d_in[13];
    const float* fW3 = (const float*)d_in[14]; const float* fb3 = (const float*)d_in[15];
    const float* oW1 = (const float*)d_in[16]; const float* ob1 = (const float*)d_in[17];
    const float* oW2 = (const float*)d_in[18]; const float* ob2 = (const float*)d_in[19];
    const float* oW3 = (const float*)d_in[20]; const float* ob3 = (const float*)d_in[21];
    float* out = (float*)d_out;

    const int HEAD_SMEM = (128 * SPAD + 96 * SPAD + 128 * 96 + 96 * 64 + 64 * 48
                           + 96 + 64 + 48) * 4;
    cudaFuncSetAttribute(athx_lstm_mma, cudaFuncAttributeMaxDynamicSharedMemorySize, SM_TOTAL);
    cudaFuncSetAttribute(athx_head_kernel, cudaFuncAttributeMaxDynamicSharedMemorySize, HEAD_SMEM);

    athx_transpose_kernel<<<dim3(NS / 64, 3, 32), dim3(32, 8)>>>(X_obs, 32, 0);
    athx_transpose_kernel<<<dim3(NS / 64, 3, 56), dim3(32, 8)>>>(X_wrf, 56, 1);

    athx_lstm_mma<<<128, 512, SM_TOTAL>>>(oWih, oWhh, obih, obhh,
                                          wWih, wWhh, wbih, wbhh);

    athx_head_kernel<<<dim3(NS / 128, 2), 512, HEAD_SMEM>>>(
        fW1, fb1, fW2, fb2, fW3, fb3,
        oW1, ob1, oW2, ob2, oW3, ob3, out);
}